// round 1
// baseline (speedup 1.0000x reference)
#include <cuda_runtime.h>

// SobelLoss: loss = mean over 3 directions of mean(|sobel_d(moved) - sobel_d(label)|)
//          = sum_{voxels,d} |conv_d(moved - label)| / (3*N)
// Shapes: moved/label = (B=2, 1, D=160, H=192, W=160) fp32, zero padding.
// Sobel kernels are separable: smooth S=[1,2,1] on two axes, deriv D=[-1,0,1] on one.

#define DIMX 160
#define DIMY 192
#define DIMZ 160
#define NBATCH 2

#define TX 32           // threads x
#define TY 8            // threads y
#define OY 16           // output rows per block (2 per thread)
#define ZCHUNK 32       // z planes per block
#define NZCH (DIMZ / ZCHUNK)   // 5

#define TILE_W (TX + 2)        // 34
#define TILE_H (OY + 2)        // 18
#define TILE_N (TILE_W * TILE_H)

// 1 / (3 * B*D*H*W) = 1 / 29491200
#define SCALE 3.3908420632258286e-08f

__global__ void sobel_init_out(float* out) { *out = 0.0f; }

__launch_bounds__(TX * TY, 8)
__global__ void sobel_loss_kernel(const float* __restrict__ moved,
                                  const float* __restrict__ label,
                                  float* __restrict__ out)
{
    __shared__ float tile[2][TILE_H][TILE_W];

    const int tx  = threadIdx.x;
    const int ty  = threadIdx.y;
    const int tid = ty * TX + tx;

    const int bx = blockIdx.x;
    const int by = blockIdx.y;
    const int b  = blockIdx.z / NZCH;
    const int z0 = (blockIdx.z % NZCH) * ZCHUNK;

    const int gx0 = bx * TX - 1;   // global x of tile col 0
    const int gy0 = by * OY - 1;   // global y of tile row 0
    const size_t base_b = (size_t)b * DIMZ * DIMY * DIMX;

    // ---- plane loader: diff = moved - label with zero padding ----
    auto load_plane = [&](int z, int buf) {
        float* dst = &tile[buf][0][0];
        if (z < 0 || z >= DIMZ) {
            #pragma unroll
            for (int i = tid; i < TILE_N; i += TX * TY)
                dst[i] = 0.0f;
        } else {
            const size_t basez = base_b + (size_t)z * (DIMY * DIMX);
            #pragma unroll
            for (int i = tid; i < TILE_N; i += TX * TY) {
                int row = i / TILE_W;
                int col = i - row * TILE_W;
                int gy = gy0 + row;
                int gx = gx0 + col;
                float v = 0.0f;
                if ((unsigned)gy < (unsigned)DIMY && (unsigned)gx < (unsigned)DIMX) {
                    size_t idx = basez + (size_t)gy * DIMX + (size_t)gx;
                    v = __ldg(moved + idx) - __ldg(label + idx);
                }
                dst[i] = v;
            }
        }
    };

    // ---- in-plane separable partials for this thread's two output rows ----
    // For output rows A (sy = 2*ty+1) and B (sy = 2*ty+2), using tile rows 2*ty .. 2*ty+3:
    //   s[r] = x(-1) + 2 x(0) + x(+1)   (smooth in x)
    //   d[r] = x(+1) - x(-1)            (deriv  in x)
    //   p = Sy*Dx, q = Dy*Sx, r = Sy*Sx
    auto compute_pqr = [&](int buf,
                           float& pA, float& qA, float& rA,
                           float& pB, float& qB, float& rB) {
        float s[4], d[4];
        #pragma unroll
        for (int r = 0; r < 4; r++) {
            float a = tile[buf][2 * ty + r][tx];
            float c = tile[buf][2 * ty + r][tx + 1];
            float e = tile[buf][2 * ty + r][tx + 2];
            s[r] = a + 2.0f * c + e;
            d[r] = e - a;
        }
        pA = d[0] + 2.0f * d[1] + d[2];
        qA = s[2] - s[0];
        rA = s[0] + 2.0f * s[1] + s[2];
        pB = d[1] + 2.0f * d[2] + d[3];
        qB = s[3] - s[1];
        rB = s[1] + 2.0f * s[2] + s[3];
    };

    // ---- prologue: planes z0-1 and z0 ----
    load_plane(z0 - 1, 1);   // (z0-1) is odd parity since z0 % 32 == 0
    load_plane(z0,     0);
    __syncthreads();

    float pA0, qA0, rA0, pB0, qB0, rB0;
    float pA1, qA1, rA1, pB1, qB1, rB1;
    compute_pqr(1, pA0, qA0, rA0, pB0, qB0, rB0);
    compute_pqr(0, pA1, qA1, rA1, pB1, qB1, rB1);

    float acc = 0.0f;

    // ---- rolling z loop: at iteration z we emit output plane z-1 ----
    for (int z = z0 + 1; z <= z0 + ZCHUNK; ++z) {
        __syncthreads();                 // all reads of plane z-2 done
        load_plane(z, z & 1);            // overwrite buffer holding plane z-2
        __syncthreads();

        float pA2, qA2, rA2, pB2, qB2, rB2;
        compute_pqr(z & 1, pA2, qA2, rA2, pB2, qB2, rB2);

        acc += fabsf(pA0 + 2.0f * pA1 + pA2)   // |Gx| row A
             + fabsf(qA0 + 2.0f * qA1 + qA2)   // |Gy| row A
             + fabsf(rA2 - rA0);               // |Gz| row A
        acc += fabsf(pB0 + 2.0f * pB1 + pB2)
             + fabsf(qB0 + 2.0f * qB1 + qB2)
             + fabsf(rB2 - rB0);

        pA0 = pA1; qA0 = qA1; rA0 = rA1;
        pA1 = pA2; qA1 = qA2; rA1 = rA2;
        pB0 = pB1; qB0 = qB1; rB0 = rB1;
        pB1 = pB2; qB1 = qB2; rB1 = rB2;
    }

    // ---- block reduction + global atomic ----
    #pragma unroll
    for (int o = 16; o > 0; o >>= 1)
        acc += __shfl_down_sync(0xFFFFFFFFu, acc, o);

    __shared__ float wsum[TX * TY / 32];
    if ((tid & 31) == 0) wsum[tid >> 5] = acc;
    __syncthreads();

    if (tid < (TX * TY / 32)) {
        float v = wsum[tid];
        #pragma unroll
        for (int o = (TX * TY / 64); o > 0; o >>= 1)
            v += __shfl_down_sync(0xFFu, v, o);
        if (tid == 0)
            atomicAdd(out, v * SCALE);
    }
}

extern "C" void kernel_launch(void* const* d_in, const int* in_sizes, int n_in,
                              void* d_out, int out_size)
{
    const float* moved = (const float*)d_in[0];
    const float* label = (const float*)d_in[1];
    float* out = (float*)d_out;

    sobel_init_out<<<1, 1>>>(out);

    dim3 grid(DIMX / TX, DIMY / OY, NBATCH * NZCH);   // (5, 12, 10)
    dim3 block(TX, TY);                               // (32, 8)
    sobel_loss_kernel<<<grid, block>>>(moved, label, out);
}

// round 2
// speedup vs baseline: 1.2605x; 1.2605x over previous
#include <cuda_runtime.h>

// SobelLoss: loss = sum_{voxels,d in {x,y,z}} |conv_d(moved - label)| / (3*N)
// Shapes: (B=2, 1, D=160, H=192, W=160) fp32, zero padding.
// Sobel separable: S=[1,2,1] smooth, D=[-1,0,1] derivative.

#define DIMX 160
#define DIMY 192
#define DIMZ 160
#define NBATCH 2
#define PLANE (DIMY * DIMX)

#define TX 32           // threads x
#define TY 8            // threads y
#define NT (TX * TY)    // 256
#define OY 16           // output rows per block (2 per thread)
#define ZCHUNK 16       // z planes per block
#define NZCH (DIMZ / ZCHUNK)   // 10

#define TILE_W (TX + 2)        // 34
#define TILE_H (OY + 2)        // 18
#define TILE_N (TILE_W * TILE_H)   // 612
#define NLD ((TILE_N + NT - 1) / NT)  // 3 load slots per thread

// 1 / (3 * B*D*H*W) = 1 / 29491200
#define SCALE 3.3908420632258286e-08f

__global__ void sobel_init_out(float* out) { *out = 0.0f; }

__launch_bounds__(NT)
__global__ void sobel_loss_kernel(const float* __restrict__ moved,
                                  const float* __restrict__ label,
                                  float* __restrict__ out)
{
    __shared__ float tile[2][TILE_H][TILE_W];

    const int tx  = threadIdx.x;
    const int ty  = threadIdx.y;
    const int tid = ty * TX + tx;

    const int b  = blockIdx.z / NZCH;
    const int z0 = (blockIdx.z % NZCH) * ZCHUNK;

    const int gx0 = blockIdx.x * TX - 1;   // global x of tile col 0
    const int gy0 = blockIdx.y * OY - 1;   // global y of tile row 0

    const float* mb = moved + (size_t)b * DIMZ * PLANE;
    const float* lb = label + (size_t)b * DIMZ * PLANE;

    // ---- precompute per-slot in-plane gmem offsets + validity (z-invariant) ----
    int  goff[NLD];
    bool gvalid[NLD];
    #pragma unroll
    for (int i = 0; i < NLD; i++) {
        int idx = tid + i * NT;
        int row = idx / TILE_W;
        int col = idx - row * TILE_W;
        int gy = gy0 + row;
        int gx = gx0 + col;
        gvalid[i] = (idx < TILE_N) &&
                    ((unsigned)gy < (unsigned)DIMY) &&
                    ((unsigned)gx < (unsigned)DIMX);
        goff[i] = gy * DIMX + gx;
    }

    float r[NLD];   // prefetched diff values for the next plane

    // fetch plane z into registers (diff, with zero padding)
    auto fetch = [&](int z) {
        const bool zok = ((unsigned)z < (unsigned)DIMZ);
        const int zb = z * PLANE;
        #pragma unroll
        for (int i = 0; i < NLD; i++) {
            float v = 0.0f;
            if (zok && gvalid[i]) {
                int idx = zb + goff[i];
                v = __ldg(mb + idx) - __ldg(lb + idx);
            }
            r[i] = v;
        }
    };

    // spill registers into smem buffer
    auto store = [&](int buf) {
        float* dst = &tile[buf][0][0];
        #pragma unroll
        for (int i = 0; i < NLD; i++) {
            int idx = tid + i * NT;
            if (idx < TILE_N) dst[idx] = r[i];
        }
    };

    // in-plane separable partials for this thread's two output rows:
    //   p = Sy*Dx, q = Dy*Sx, rr = Sy*Sx
    auto compute_pqr = [&](int buf,
                           float& pA, float& qA, float& rA,
                           float& pB, float& qB, float& rB) {
        float s[4], d[4];
        #pragma unroll
        for (int rr = 0; rr < 4; rr++) {
            float a = tile[buf][2 * ty + rr][tx];
            float c = tile[buf][2 * ty + rr][tx + 1];
            float e = tile[buf][2 * ty + rr][tx + 2];
            s[rr] = a + 2.0f * c + e;
            d[rr] = e - a;
        }
        pA = d[0] + 2.0f * d[1] + d[2];
        qA = s[2] - s[0];
        rA = s[0] + 2.0f * s[1] + s[2];
        pB = d[1] + 2.0f * d[2] + d[3];
        qB = s[3] - s[1];
        rB = s[1] + 2.0f * s[2] + s[3];
    };

    // ---- prologue: planes z0-1, z0 into smem; z0+1 prefetched in regs ----
    fetch(z0 - 1); store(1);   // z0 is even (multiple of 16) -> (z0-1)&1 == 1
    fetch(z0);     store(0);
    __syncthreads();

    float pA0, qA0, rA0, pB0, qB0, rB0;
    float pA1, qA1, rA1, pB1, qB1, rB1;
    compute_pqr(1, pA0, qA0, rA0, pB0, qB0, rB0);
    compute_pqr(0, pA1, qA1, rA1, pB1, qB1, rB1);

    fetch(z0 + 1);   // prefetch; lands before loop's first store

    float acc = 0.0f;

    // ---- rolling z loop: registers hold plane z; emit output plane z-1 ----
    for (int z = z0 + 1; z <= z0 + ZCHUNK; ++z) {
        __syncthreads();                 // prior compute (readers of buf z&1's old data) done
        store(z & 1);                    // write plane z over plane z-2
        if (z < z0 + ZCHUNK) fetch(z + 1);   // prefetch next plane (no smem dep)
        __syncthreads();

        float pA2, qA2, rA2, pB2, qB2, rB2;
        compute_pqr(z & 1, pA2, qA2, rA2, pB2, qB2, rB2);

        acc += fabsf(pA0 + 2.0f * pA1 + pA2)   // |Gx| row A
             + fabsf(qA0 + 2.0f * qA1 + qA2)   // |Gy| row A
             + fabsf(rA2 - rA0);               // |Gz| row A
        acc += fabsf(pB0 + 2.0f * pB1 + pB2)
             + fabsf(qB0 + 2.0f * qB1 + qB2)
             + fabsf(rB2 - rB0);

        pA0 = pA1; qA0 = qA1; rA0 = rA1;
        pA1 = pA2; qA1 = qA2; rA1 = rA2;
        pB0 = pB1; qB0 = qB1; rB0 = rB1;
        pB1 = pB2; qB1 = qB2; rB1 = rB2;
    }

    // ---- block reduction + global atomic ----
    #pragma unroll
    for (int o = 16; o > 0; o >>= 1)
        acc += __shfl_down_sync(0xFFFFFFFFu, acc, o);

    __shared__ float wsum[NT / 32];
    if ((tid & 31) == 0) wsum[tid >> 5] = acc;
    __syncthreads();

    if (tid < (NT / 32)) {
        float v = wsum[tid];
        #pragma unroll
        for (int o = (NT / 64); o > 0; o >>= 1)
            v += __shfl_down_sync(0xFFu, v, o);
        if (tid == 0)
            atomicAdd(out, v * SCALE);
    }
}

extern "C" void kernel_launch(void* const* d_in, const int* in_sizes, int n_in,
                              void* d_out, int out_size)
{
    const float* moved = (const float*)d_in[0];
    const float* label = (const float*)d_in[1];
    float* out = (float*)d_out;

    sobel_init_out<<<1, 1>>>(out);

    dim3 grid(DIMX / TX, DIMY / OY, NBATCH * NZCH);   // (5, 12, 20) = 1200 CTAs
    dim3 block(TX, TY);                               // (32, 8)
    sobel_loss_kernel<<<grid, block>>>(moved, label, out);
}

// round 4
// speedup vs baseline: 1.3238x; 1.0502x over previous
#include <cuda_runtime.h>

// SobelLoss: loss = sum_{voxels,d in {x,y,z}} |conv_d(moved - label)| / (3*N)
// Shapes: (B=2, 1, D=160, H=192, W=160) fp32, zero padding.
// Sobel separable: S=[1,2,1] smooth, D=[-1,0,1] derivative.

#define DIMX 160
#define DIMY 192
#define DIMZ 160
#define NBATCH 2
#define PLANE (DIMY * DIMX)

#define TX 32           // threads x
#define TY 8            // threads y
#define NT (TX * TY)    // 256
#define OY 16           // output rows per block (2 per thread)
#define ZCHUNK 16       // z planes per block
#define NZCH (DIMZ / ZCHUNK)   // 10

#define TILE_W (TX + 2)        // 34
#define TILE_H (OY + 2)        // 18
#define TILE_N (TILE_W * TILE_H)   // 612
#define NLD 3                  // load slots per thread (612/256 -> 3)
#define NBUF 3                 // triple buffer: one syncthreads per plane

// 1 / (3 * B*D*H*W) = 1 / 29491200
#define SCALE 3.3908420632258286e-08f

__global__ void sobel_init_out(float* out) { *out = 0.0f; }

__launch_bounds__(NT, 8)   // force <=32 regs -> 8 CTAs/SM -> grid fits in ONE wave
__global__ void sobel_loss_kernel(const float* __restrict__ moved,
                                  const float* __restrict__ label,
                                  float* __restrict__ out)
{
    __shared__ float tile[NBUF][TILE_N];

    const int tx  = threadIdx.x;
    const int ty  = threadIdx.y;
    const int tid = ty * TX + tx;

    const int b  = blockIdx.z / NZCH;
    const int z0 = (blockIdx.z % NZCH) * ZCHUNK;

    const int gx0 = blockIdx.x * TX - 1;   // global x of tile col 0
    const int gy0 = blockIdx.y * OY - 1;   // global y of tile row 0

    const float* mb = moved + (size_t)b * DIMZ * PLANE;
    const float* lb = label + (size_t)b * DIMZ * PLANE;

    // per-slot in-plane gmem offsets; -1 sentinel = out of bounds / beyond tile
    int goff[NLD];
    #pragma unroll
    for (int i = 0; i < NLD; i++) {
        int idx = tid + i * NT;
        int row = idx / TILE_W;
        int col = idx - row * TILE_W;
        int gy = gy0 + row;
        int gx = gx0 + col;
        bool ok = (idx < TILE_N) &&
                  ((unsigned)gy < (unsigned)DIMY) &&
                  ((unsigned)gx < (unsigned)DIMX);
        goff[i] = ok ? (gy * DIMX + gx) : -1;
    }

    float r[NLD];   // prefetched diff values

    auto fetch = [&](int z) {
        const bool zok = ((unsigned)z < (unsigned)DIMZ);
        const int zb = z * PLANE;
        float mv[NLD], lv[NLD];
        #pragma unroll
        for (int i = 0; i < NLD; i++) {
            bool ok = zok && (goff[i] >= 0);
            mv[i] = ok ? __ldg(mb + zb + goff[i]) : 0.0f;
            lv[i] = ok ? __ldg(lb + zb + goff[i]) : 0.0f;
        }
        #pragma unroll
        for (int i = 0; i < NLD; i++) r[i] = mv[i] - lv[i];
    };

    auto store = [&](int buf) {
        float* dst = tile[buf];
        dst[tid]      = r[0];
        dst[tid + NT] = r[1];
        if (tid < TILE_N - 2 * NT) dst[tid + 2 * NT] = r[2];
    };

    // in-plane separable partials for this thread's two output rows:
    //   p = Sy*Dx, q = Dy*Sx, rr = Sy*Sx
    auto compute_pqr = [&](int buf,
                           float& pA, float& qA, float& rA,
                           float& pB, float& qB, float& rB) {
        float s[4], d[4];
        const float* base = tile[buf] + (2 * ty) * TILE_W + tx;
        #pragma unroll
        for (int rr = 0; rr < 4; rr++) {
            float a = base[rr * TILE_W];
            float c = base[rr * TILE_W + 1];
            float e = base[rr * TILE_W + 2];
            s[rr] = a + 2.0f * c + e;
            d[rr] = e - a;
        }
        pA = d[0] + 2.0f * d[1] + d[2];
        qA = s[2] - s[0];
        rA = s[0] + 2.0f * s[1] + s[2];
        pB = d[1] + 2.0f * d[2] + d[3];
        qB = s[3] - s[1];
        rB = s[1] + 2.0f * s[2] + s[3];
    };

    // ---- prologue: planes z0-1, z0, z0+1 into their buffers (plane p -> buf p%3) ----
    fetch(z0 - 1); store((z0 + 2) % NBUF);   // (z0-1) mod 3, kept nonnegative
    fetch(z0);     store(z0 % NBUF);
    fetch(z0 + 1); store((z0 + 1) % NBUF);
    __syncthreads();

    float pA0, qA0, rA0, pB0, qB0, rB0;
    float pA1, qA1, rA1, pB1, qB1, rB1;
    compute_pqr((z0 + 2) % NBUF, pA0, qA0, rA0, pB0, qB0, rB0);   // plane z0-1
    compute_pqr(z0 % NBUF,       pA1, qA1, rA1, pB1, qB1, rB1);   // plane z0

    fetch(z0 + 2);   // prefetch: at iteration z, registers hold plane z+1

    float acc = 0.0f;
    const int zend = z0 + ZCHUNK;

    // ---- rolling z loop: ONE syncthreads per plane (3-buffer pipeline) ----
    // iter z: store plane z+1 into buf (z+1)%3 (over plane z-2),
    //         prefetch plane z+2, compute plane z, emit output plane z-1
    for (int z = z0 + 1; z <= zend; ++z) {
        __syncthreads();                 // all compute(z-1) done everywhere
        if (z < zend) {
            store((z + 1) % NBUF);       // plane z+1 -> its buffer (FIX: was (z+2)%NBUF)
            if (z + 2 <= zend) fetch(z + 2);
        }

        float pA2, qA2, rA2, pB2, qB2, rB2;
        compute_pqr(z % NBUF, pA2, qA2, rA2, pB2, qB2, rB2);      // plane z

        acc += fabsf(pA0 + 2.0f * pA1 + pA2)   // |Gx| row A
             + fabsf(qA0 + 2.0f * qA1 + qA2)   // |Gy| row A
             + fabsf(rA2 - rA0);               // |Gz| row A
        acc += fabsf(pB0 + 2.0f * pB1 + pB2)
             + fabsf(qB0 + 2.0f * qB1 + qB2)
             + fabsf(rB2 - rB0);

        pA0 = pA1; qA0 = qA1; rA0 = rA1;
        pA1 = pA2; qA1 = qA2; rA1 = rA2;
        pB0 = pB1; qB0 = qB1; rB0 = rB1;
        pB1 = pB2; qB1 = qB2; rB1 = rB2;
    }

    // ---- block reduction + global atomic ----
    #pragma unroll
    for (int o = 16; o > 0; o >>= 1)
        acc += __shfl_down_sync(0xFFFFFFFFu, acc, o);

    __shared__ float wsum[NT / 32];
    if ((tid & 31) == 0) wsum[tid >> 5] = acc;
    __syncthreads();

    if (tid < (NT / 32)) {
        float v = wsum[tid];
        #pragma unroll
        for (int o = (NT / 64); o > 0; o >>= 1)
            v += __shfl_down_sync(0xFFu, v, o);
        if (tid == 0)
            atomicAdd(out, v * SCALE);
    }
}

extern "C" void kernel_launch(void* const* d_in, const int* in_sizes, int n_in,
                              void* d_out, int out_size)
{
    const float* moved = (const float*)d_in[0];
    const float* label = (const float*)d_in[1];
    float* out = (float*)d_out;

    sobel_init_out<<<1, 1>>>(out);

    dim3 grid(DIMX / TX, DIMY / OY, NBATCH * NZCH);   // (5, 12, 20) = 1200 CTAs
    dim3 block(TX, TY);                               // (32, 8)
    sobel_loss_kernel<<<grid, block>>>(moved, label, out);
}

// round 5
// speedup vs baseline: 1.4167x; 1.0702x over previous
#include <cuda_runtime.h>

// SobelLoss: loss = sum_{voxels,d in {x,y,z}} |conv_d(moved - label)| / (3*N)
// Shapes: (B=2, 1, D=160, H=192, W=160) fp32, zero padding.
// Sobel separable: S=[1,2,1] smooth, D=[-1,0,1] derivative.

#define DIMX 160
#define DIMY 192
#define DIMZ 160
#define NBATCH 2
#define PLANE (DIMY * DIMX)

#define TX 32           // threads x
#define TY 8            // threads y
#define NT (TX * TY)    // 256
#define OY 16           // output rows per block (2 per thread)
#define ZCHUNK 16       // z planes per block
#define NZCH (DIMZ / ZCHUNK)   // 10

#define TILE_W 40              // raw tile cols, 16B-aligned: gx in [32bx-4, 32bx+35]
#define TILE_W4 (TILE_W / 4)   // 10 float4 per row
#define TILE_H (OY + 2)        // 18
#define NSLOT (TILE_H * TILE_W4)   // 180 float4 slots per plane
#define XOFF 3                 // out col tx reads raw cols tx+3 .. tx+5 (gx-1..gx+1)
#define NBUF 3                 // triple buffer: one syncthreads per plane

// 1 / (3 * B*D*H*W) = 1 / 29491200
#define SCALE 3.3908420632258286e-08f

__global__ void sobel_init_out(float* out) { *out = 0.0f; }

__launch_bounds__(NT, 8)   // 8 CTAs/SM -> 1200-CTA grid fits in ONE wave
__global__ void sobel_loss_kernel(const float* __restrict__ moved,
                                  const float* __restrict__ label,
                                  float* __restrict__ out)
{
    __shared__ float4 tile4[NBUF][NSLOT];   // 3 x 18 x 40 floats, 16B aligned

    const int tx  = threadIdx.x;
    const int ty  = threadIdx.y;
    const int tid = ty * TX + tx;

    const int b  = blockIdx.z / NZCH;
    const int z0 = (blockIdx.z % NZCH) * ZCHUNK;

    const int gy0 = blockIdx.y * OY - 1;        // global y of tile row 0
    const int gxv0 = blockIdx.x * TX - 4;       // global x of tile col 0 (16B aligned)

    const float* mb = moved + (size_t)b * DIMZ * PLANE;
    const float* lb = label + (size_t)b * DIMZ * PLANE;

    // ---- this thread's single float4 load slot (z-invariant) ----
    const int  row  = tid / TILE_W4;            // 0..17 (tid<180), garbage otherwise
    const int  vc   = tid - row * TILE_W4;      // 0..9
    const int  gy   = gy0 + row;
    const int  gxv  = gxv0 + vc * 4;            // aligned; whole vec in/out of bounds
    const bool okxy = (tid < NSLOT) &&
                      ((unsigned)gy  < (unsigned)DIMY) &&
                      ((unsigned)gxv < (unsigned)DIMX);
    const int  off  = gy * DIMX + gxv;          // element offset within a plane

    float4 r4;   // prefetched diff values (one vec4 per thread)

    auto fetch = [&](int z) {
        if (okxy && (unsigned)z < (unsigned)DIMZ) {
            const float4* m4 = (const float4*)(mb + (size_t)z * PLANE + off);
            const float4* l4 = (const float4*)(lb + (size_t)z * PLANE + off);
            float4 m = __ldg(m4);
            float4 l = __ldg(l4);
            r4.x = m.x - l.x; r4.y = m.y - l.y;
            r4.z = m.z - l.z; r4.w = m.w - l.w;
        } else {
            r4 = make_float4(0.f, 0.f, 0.f, 0.f);
        }
    };

    auto store = [&](int buf) {
        if (tid < NSLOT) tile4[buf][tid] = r4;
    };

    // in-plane separable partials for this thread's two output rows:
    //   p = Sy*Dx, q = Dy*Sx, rr = Sy*Sx
    auto compute_pqr = [&](int buf,
                           float& pA, float& qA, float& rA,
                           float& pB, float& qB, float& rB) {
        float s[4], d[4];
        const float* base = (const float*)tile4[buf] + (2 * ty) * TILE_W + (tx + XOFF);
        #pragma unroll
        for (int rr = 0; rr < 4; rr++) {
            float a = base[rr * TILE_W];
            float c = base[rr * TILE_W + 1];
            float e = base[rr * TILE_W + 2];
            s[rr] = a + 2.0f * c + e;
            d[rr] = e - a;
        }
        pA = d[0] + 2.0f * d[1] + d[2];
        qA = s[2] - s[0];
        rA = s[0] + 2.0f * s[1] + s[2];
        pB = d[1] + 2.0f * d[2] + d[3];
        qB = s[3] - s[1];
        rB = s[1] + 2.0f * s[2] + s[3];
    };

    // ---- prologue: planes z0-1, z0, z0+1 into their buffers (plane p -> buf p%3) ----
    fetch(z0 - 1); store((z0 + 2) % NBUF);   // (z0-1) mod 3, kept nonnegative
    fetch(z0);     store(z0 % NBUF);
    fetch(z0 + 1); store((z0 + 1) % NBUF);
    __syncthreads();

    float pA0, qA0, rA0, pB0, qB0, rB0;
    float pA1, qA1, rA1, pB1, qB1, rB1;
    compute_pqr((z0 + 2) % NBUF, pA0, qA0, rA0, pB0, qB0, rB0);   // plane z0-1
    compute_pqr(z0 % NBUF,       pA1, qA1, rA1, pB1, qB1, rB1);   // plane z0

    fetch(z0 + 2);   // prefetch: at iteration z, registers hold plane z+1

    float acc = 0.0f;
    const int zend = z0 + ZCHUNK;

    // ---- rolling z loop: ONE syncthreads per plane (3-buffer pipeline) ----
    // iter z: store plane z+1 into buf (z+1)%3 (over plane z-2),
    //         prefetch plane z+2, compute plane z, emit output plane z-1
    for (int z = z0 + 1; z <= zend; ++z) {
        __syncthreads();                 // all compute(z-1) done everywhere
        if (z < zend) {
            store((z + 1) % NBUF);       // plane z+1 -> its buffer
            if (z + 2 <= zend) fetch(z + 2);
        }

        float pA2, qA2, rA2, pB2, qB2, rB2;
        compute_pqr(z % NBUF, pA2, qA2, rA2, pB2, qB2, rB2);      // plane z

        acc += fabsf(pA0 + 2.0f * pA1 + pA2)   // |Gx| row A
             + fabsf(qA0 + 2.0f * qA1 + qA2)   // |Gy| row A
             + fabsf(rA2 - rA0);               // |Gz| row A
        acc += fabsf(pB0 + 2.0f * pB1 + pB2)
             + fabsf(qB0 + 2.0f * qB1 + qB2)
             + fabsf(rB2 - rB0);

        pA0 = pA1; qA0 = qA1; rA0 = rA1;
        pA1 = pA2; qA1 = qA2; rA1 = rA2;
        pB0 = pB1; qB0 = qB1; rB0 = rB1;
        pB1 = pB2; qB1 = qB2; rB1 = rB2;
    }

    // ---- block reduction + global atomic ----
    #pragma unroll
    for (int o = 16; o > 0; o >>= 1)
        acc += __shfl_down_sync(0xFFFFFFFFu, acc, o);

    __shared__ float wsum[NT / 32];
    if ((tid & 31) == 0) wsum[tid >> 5] = acc;
    __syncthreads();

    if (tid < (NT / 32)) {
        float v = wsum[tid];
        #pragma unroll
        for (int o = (NT / 64); o > 0; o >>= 1)
            v += __shfl_down_sync(0xFFu, v, o);
        if (tid == 0)
            atomicAdd(out, v * SCALE);
    }
}

extern "C" void kernel_launch(void* const* d_in, const int* in_sizes, int n_in,
                              void* d_out, int out_size)
{
    const float* moved = (const float*)d_in[0];
    const float* label = (const float*)d_in[1];
    float* out = (float*)d_out;

    sobel_init_out<<<1, 1>>>(out);

    dim3 grid(DIMX / TX, DIMY / OY, NBATCH * NZCH);   // (5, 12, 20) = 1200 CTAs
    dim3 block(TX, TY);                               // (32, 8)
    sobel_loss_kernel<<<grid, block>>>(moved, label, out);
}

// round 6
// speedup vs baseline: 1.4182x; 1.0011x over previous
#include <cuda_runtime.h>

// SobelLoss: loss = sum_{voxels,d in {x,y,z}} |conv_d(moved - label)| / (3*N)
// Shapes: (B=2, 1, D=160, H=192, W=160) fp32, zero padding.
// Sobel separable: S=[1,2,1] smooth, D=[-1,0,1] derivative.

#define DIMX 160
#define DIMY 192
#define DIMZ 160
#define NBATCH 2
#define PLANE (DIMY * DIMX)

#define TX 32           // threads x
#define TY 8            // threads y
#define NT (TX * TY)    // 256
#define OY 16           // output rows per block (2 per thread)
#define ZCHUNK 16       // z planes per block
#define NZCH (DIMZ / ZCHUNK)   // 10

#define TILE_W 40              // raw tile cols, 16B-aligned: gx in [32bx-4, 32bx+35]
#define TILE_W4 (TILE_W / 4)   // 10 float4 per row
#define TILE_H (OY + 2)        // 18
#define NSLOT (TILE_H * TILE_W4)   // 180 float4 slots per plane
#define XOFF 3                 // out col tx reads raw cols tx+3 .. tx+5 (gx-1..gx+1)
#define NBUF 3                 // triple buffer: one syncthreads per plane

// 1 / (3 * B*D*H*W) = 1 / 29491200
#define SCALE 3.3908420632258286e-08f

__global__ void sobel_init_out(float* out) { *out = 0.0f; }

__launch_bounds__(NT, 8)   // 8 CTAs/SM -> 1200-CTA grid fits in ONE wave
__global__ void sobel_loss_kernel(const float* __restrict__ moved,
                                  const float* __restrict__ label,
                                  float* __restrict__ out)
{
    __shared__ float4 tile4[NBUF][NSLOT];   // 3 x 18 x 40 floats, 16B aligned

    const int tx  = threadIdx.x;
    const int ty  = threadIdx.y;
    const int tid = ty * TX + tx;

    const int b  = blockIdx.z / NZCH;
    const int z0 = (blockIdx.z % NZCH) * ZCHUNK;

    const int gy0 = blockIdx.y * OY - 1;        // global y of tile row 0
    const int gxv0 = blockIdx.x * TX - 4;       // global x of tile col 0 (16B aligned)

    const float* mb = moved + (size_t)b * DIMZ * PLANE;
    const float* lb = label + (size_t)b * DIMZ * PLANE;

    // ---- this thread's single float4 load slot (z-invariant) ----
    const int  row  = tid / TILE_W4;            // 0..17 (tid<180), garbage otherwise
    const int  vc   = tid - row * TILE_W4;      // 0..9
    const int  gy   = gy0 + row;
    const int  gxv  = gxv0 + vc * 4;            // aligned; whole vec in/out of bounds
    const bool okxy = (tid < NSLOT) &&
                      ((unsigned)gy  < (unsigned)DIMY) &&
                      ((unsigned)gxv < (unsigned)DIMX);
    const int  off  = gy * DIMX + gxv;          // element offset within a plane

    float4 r4;   // prefetched diff values (one vec4 per thread)

    auto fetch = [&](int z) {
        if (okxy && (unsigned)z < (unsigned)DIMZ) {
            const float4* m4 = (const float4*)(mb + (size_t)z * PLANE + off);
            const float4* l4 = (const float4*)(lb + (size_t)z * PLANE + off);
            float4 m = __ldg(m4);
            float4 l = __ldg(l4);
            r4.x = m.x - l.x; r4.y = m.y - l.y;
            r4.z = m.z - l.z; r4.w = m.w - l.w;
        } else {
            r4 = make_float4(0.f, 0.f, 0.f, 0.f);
        }
    };

    auto store = [&](int buf) {
        if (tid < NSLOT) tile4[buf][tid] = r4;
    };

    // in-plane separable partials for this thread's two output rows:
    //   p = Sy*Dx, q = Dy*Sx, rr = Sy*Sx
    auto compute_pqr = [&](int buf,
                           float& pA, float& qA, float& rA,
                           float& pB, float& qB, float& rB) {
        float s[4], d[4];
        const float* base = (const float*)tile4[buf] + (2 * ty) * TILE_W + (tx + XOFF);
        #pragma unroll
        for (int rr = 0; rr < 4; rr++) {
            float a = base[rr * TILE_W];
            float c = base[rr * TILE_W + 1];
            float e = base[rr * TILE_W + 2];
            s[rr] = a + 2.0f * c + e;
            d[rr] = e - a;
        }
        pA = d[0] + 2.0f * d[1] + d[2];
        qA = s[2] - s[0];
        rA = s[0] + 2.0f * s[1] + s[2];
        pB = d[1] + 2.0f * d[2] + d[3];
        qB = s[3] - s[1];
        rB = s[1] + 2.0f * s[2] + s[3];
    };

    // ---- prologue: planes z0-1, z0, z0+1 into their buffers (plane p -> buf p%3) ----
    fetch(z0 - 1); store((z0 + 2) % NBUF);   // (z0-1) mod 3, kept nonnegative
    fetch(z0);     store(z0 % NBUF);
    fetch(z0 + 1); store((z0 + 1) % NBUF);
    __syncthreads();

    float pA0, qA0, rA0, pB0, qB0, rB0;
    float pA1, qA1, rA1, pB1, qB1, rB1;
    compute_pqr((z0 + 2) % NBUF, pA0, qA0, rA0, pB0, qB0, rB0);   // plane z0-1
    compute_pqr(z0 % NBUF,       pA1, qA1, rA1, pB1, qB1, rB1);   // plane z0

    fetch(z0 + 2);   // prefetch: at iteration z, registers hold plane z+1

    float acc = 0.0f;
    const int zend = z0 + ZCHUNK;

    // ---- rolling z loop: ONE syncthreads per plane (3-buffer pipeline) ----
    // iter z: store plane z+1 into buf (z+1)%3 (over plane z-2),
    //         prefetch plane z+2, compute plane z, emit output plane z-1
    for (int z = z0 + 1; z <= zend; ++z) {
        __syncthreads();                 // all compute(z-1) done everywhere
        if (z < zend) {
            store((z + 1) % NBUF);       // plane z+1 -> its buffer
            if (z + 2 <= zend) fetch(z + 2);
        }

        float pA2, qA2, rA2, pB2, qB2, rB2;
        compute_pqr(z % NBUF, pA2, qA2, rA2, pB2, qB2, rB2);      // plane z

        acc += fabsf(pA0 + 2.0f * pA1 + pA2)   // |Gx| row A
             + fabsf(qA0 + 2.0f * qA1 + qA2)   // |Gy| row A
             + fabsf(rA2 - rA0);               // |Gz| row A
        acc += fabsf(pB0 + 2.0f * pB1 + pB2)
             + fabsf(qB0 + 2.0f * qB1 + qB2)
             + fabsf(rB2 - rB0);

        pA0 = pA1; qA0 = qA1; rA0 = rA1;
        pA1 = pA2; qA1 = qA2; rA1 = rA2;
        pB0 = pB1; qB0 = qB1; rB0 = rB1;
        pB1 = pB2; qB1 = qB2; rB1 = rB2;
    }

    // ---- block reduction + global atomic ----
    #pragma unroll
    for (int o = 16; o > 0; o >>= 1)
        acc += __shfl_down_sync(0xFFFFFFFFu, acc, o);

    __shared__ float wsum[NT / 32];
    if ((tid & 31) == 0) wsum[tid >> 5] = acc;
    __syncthreads();

    if (tid < (NT / 32)) {
        float v = wsum[tid];
        #pragma unroll
        for (int o = (NT / 64); o > 0; o >>= 1)
            v += __shfl_down_sync(0xFFu, v, o);
        if (tid == 0)
            atomicAdd(out, v * SCALE);
    }
}

extern "C" void kernel_launch(void* const* d_in, const int* in_sizes, int n_in,
                              void* d_out, int out_size)
{
    const float* moved = (const float*)d_in[0];
    const float* label = (const float*)d_in[1];
    float* out = (float*)d_out;

    sobel_init_out<<<1, 1>>>(out);

    dim3 grid(DIMX / TX, DIMY / OY, NBATCH * NZCH);   // (5, 12, 20) = 1200 CTAs
    dim3 block(TX, TY);                               // (32, 8)
    sobel_loss_kernel<<<grid, block>>>(moved, label, out);
}